// round 3
// baseline (speedup 1.0000x reference)
#include <cuda_runtime.h>
#include <math.h>

// Problem shape (fixed by reference setup_inputs)
#define BATCH 2048
#define NLABELS 50000
#define NTRIALS 64

#define ROWS_PER_BLOCK 4
#define THREADS_PER_BLOCK (ROWS_PER_BLOCK * NTRIALS)   // 256
#define NUM_BLOCKS (BATCH / ROWS_PER_BLOCK)            // 512

// Scratch for deterministic single-kernel reduction (no allocations allowed).
__device__ float g_partials[NUM_BLOCKS];
// atomicInc with limit NUM_BLOCKS-1 wraps to 0 when the last block arrives ->
// counter automatically reset for the next graph replay.
__device__ unsigned int g_arrive = 0;

// One 64-thread group (2 warps) per batch row: thread t handles trial t.
// Each thread: one coalesced idx load + one scattered gather (max MLP, minimal
// dependent chain). First accepted trial found via 2 ballots; the selected
// negative score is fetched from a shared-memory score table.
__global__ void __launch_bounds__(THREADS_PER_BLOCK)
warp_loss_fused(const float* __restrict__ inp,
                const int* __restrict__ pos_idx,
                const int* __restrict__ neg_cands,
                float* __restrict__ out)
{
    const int tid     = threadIdx.x;
    const int lane    = tid & 31;
    const int grp     = tid >> 6;            // row group within block (0..3)
    const int trial   = tid & 63;            // trial index within the row
    const int half    = (tid >> 5) & 1;      // which warp of the group
    const int row     = blockIdx.x * ROWS_PER_BLOCK + grp;

    __shared__ float    s_score[ROWS_PER_BLOCK][NTRIALS];  // per-trial neg scores
    __shared__ unsigned s_mask[ROWS_PER_BLOCK][2];         // accept ballots
    __shared__ float    s_loss[ROWS_PER_BLOCK];
    __shared__ bool     s_is_last;

    // ---- issue all loads up front (2-deep dependent chain max) ----
    const long  base  = (long)row * NLABELS;
    const int   p     = __ldg(pos_idx + row);             // broadcast within group
    const int   idx   = __ldg(neg_cands + row * NTRIALS + trial);  // coalesced
    const float pos_s = __ldg(inp + base + p);            // broadcast gather
    const float neg   = __ldg(inp + base + idx);          // scattered gather

    const bool ok = (neg >= pos_s - 1.0f);                // margin >= 0
    const unsigned m = __ballot_sync(0xffffffffu, ok);

    s_score[grp][trial] = neg;
    if (lane == 0) s_mask[grp][half] = m;
    __syncthreads();

    // ---- one thread per row computes the loss ----
    if (trial == 0) {
        const unsigned m0 = s_mask[grp][0];
        const unsigned m1 = s_mask[grp][1];
        float loss = 0.0f;
        if (m0 | m1) {
            const int first = m0 ? (__ffs(m0) - 1) : (32 + __ffs(m1) - 1);
            const float sel = s_score[grp][first];
            const float nt  = (float)(first + 1);
            const float L   = logf(floorf((float)(NLABELS - 1) / nt));
            loss = L * (1.0f - pos_s + sel);
        }
        s_loss[grp] = loss;
    }
    __syncthreads();

    // ---- block partial + last-block final reduction ----
    if (tid == 0) {
        float sum = 0.0f;
        #pragma unroll
        for (int i = 0; i < ROWS_PER_BLOCK; i++) sum += s_loss[i];
        g_partials[blockIdx.x] = sum;
        __threadfence();
        unsigned old = atomicInc(&g_arrive, NUM_BLOCKS - 1);
        s_is_last = (old == NUM_BLOCKS - 1);
    }
    __syncthreads();

    if (s_is_last) {
        // Deterministic reduction of 512 partials by 256 threads.
        __shared__ float s[THREADS_PER_BLOCK];
        float v = g_partials[tid] + g_partials[tid + THREADS_PER_BLOCK];
        s[tid] = v;
        __syncthreads();
        #pragma unroll
        for (int stride = THREADS_PER_BLOCK / 2; stride >= 1; stride >>= 1) {
            if (tid < stride) s[tid] += s[tid + stride];
            __syncthreads();
        }
        if (tid == 0) out[0] = s[0];
    }
}

extern "C" void kernel_launch(void* const* d_in, const int* in_sizes, int n_in,
                              void* d_out, int out_size)
{
    // metadata order: input (f32 [B,Y]), target (i32, UNUSED), pos_idx (i32 [B]),
    //                 neg_cands (i32 [B,T]); output f32 [1]
    const float* inp     = (const float*)d_in[0];
    const int*   pos_idx = (const int*)d_in[2];
    const int*   neg     = (const int*)d_in[3];
    float*       out     = (float*)d_out;

    warp_loss_fused<<<NUM_BLOCKS, THREADS_PER_BLOCK>>>(inp, pos_idx, neg, out);
}